// round 4
// baseline (speedup 1.0000x reference)
#include <cuda_runtime.h>
#include <cstdint>

// Problem constants (fixed by the dataset)
#define T_ 8
#define E_ 8388608
#define N_ 262144
#define F_ 64

// 8 MB scratch for segment sums, layout agg[n][t] row-major (32B per node).
// Zero-initialized at module load; gemm_kernel re-zeros it after consuming,
// so every kernel_launch invocation (and every graph replay) sees zeros.
__device__ float g_agg[(size_t)N_ * T_];

// ---------------------------------------------------------------------------
// Scatter-add: 2 edges per thread.
// Per thread: 1x int4 index load (2 int32 pairs), 8x float2 feature loads
// (coalesced 256B/warp per t), 4x red.global.add.v4.f32 into L2-resident agg.
// ---------------------------------------------------------------------------
__global__ void scatter_kernel(const float* __restrict__ feat,
                               const int4* __restrict__ idx) {
    int i = blockIdx.x * blockDim.x + threadIdx.x;     // pair index, < E_/2
    size_t e = (size_t)i * 2;

    int4 rc = __ldcs(&idx[i]);                         // (row0,col0,row1,col1)
    int row0 = rc.x & (N_ - 1);
    int row1 = rc.z & (N_ - 1);

    float2 f[T_];
    #pragma unroll
    for (int t = 0; t < T_; ++t)
        f[t] = __ldcs(reinterpret_cast<const float2*>(feat + (size_t)t * E_ + e));

    float* d0 = g_agg + (size_t)row0 * T_;
    float* d1 = g_agg + (size_t)row1 * T_;

    asm volatile("red.global.add.v4.f32 [%0], {%1,%2,%3,%4};"
                 :: "l"(d0),     "f"(f[0].x), "f"(f[1].x), "f"(f[2].x), "f"(f[3].x) : "memory");
    asm volatile("red.global.add.v4.f32 [%0], {%1,%2,%3,%4};"
                 :: "l"(d0 + 4), "f"(f[4].x), "f"(f[5].x), "f"(f[6].x), "f"(f[7].x) : "memory");
    asm volatile("red.global.add.v4.f32 [%0], {%1,%2,%3,%4};"
                 :: "l"(d1),     "f"(f[0].y), "f"(f[1].y), "f"(f[2].y), "f"(f[3].y) : "memory");
    asm volatile("red.global.add.v4.f32 [%0], {%1,%2,%3,%4};"
                 :: "l"(d1 + 4), "f"(f[4].y), "f"(f[5].y), "f"(f[6].y), "f"(f[7].y) : "memory");
}

// ---------------------------------------------------------------------------
// out[n,f] = sum_t agg[n,t] * kernel[t,f] + bias[f]; also re-zeros agg so the
// next invocation/replay starts clean (replaces the dedicated zero kernel).
// Block = 256 threads -> 32 nodes x 64 features.
// ---------------------------------------------------------------------------
__global__ void gemm_kernel(const float* __restrict__ kern,
                            const float* __restrict__ bias,
                            float* __restrict__ out) {
    __shared__ float sK[T_ * F_];   // 512 floats
    __shared__ float sA[32 * T_];   // 256 floats

    int tid = threadIdx.x;
    int nbase = blockIdx.x * 32;

    sK[tid]       = kern[tid];
    sK[tid + 256] = kern[tid + 256];
    float a = g_agg[(size_t)nbase * T_ + tid];
    sA[tid] = a;
    g_agg[(size_t)nbase * T_ + tid] = 0.0f;   // consume-and-zero
    __syncthreads();

    int f   = tid & 63;    // 0..63
    int nl0 = tid >> 6;    // 0..3
    float b = bias[f];

    #pragma unroll
    for (int i = 0; i < 8; ++i) {
        int nl = nl0 + (i << 2);         // 0..31
        float acc = b;
        #pragma unroll
        for (int t = 0; t < T_; ++t)
            acc = fmaf(sA[nl * T_ + t], sK[t * F_ + f], acc);
        out[((size_t)(nbase + nl)) * F_ + f] = acc;
    }
}

// ---------------------------------------------------------------------------
// Launch contract — inputs resolved BY ELEMENT COUNT (robust to whether the
// scalar `out_size` occupies an input slot):
//   edge_features:  T*E = 67108864 f32
//   sparse_indices: E*2 = 16777216 i32
//   kernel:         T*F = 512 f32
//   bias:           F   = 64 f32
// Output: N*F f32.
// ---------------------------------------------------------------------------
extern "C" void kernel_launch(void* const* d_in, const int* in_sizes, int n_in,
                              void* d_out, int out_size) {
    const float* feat = nullptr;
    const int4*  idx  = nullptr;
    const float* kern = nullptr;
    const float* bias = nullptr;

    for (int i = 0; i < n_in; ++i) {
        long long s = in_sizes[i];
        if      (s == (long long)T_ * E_) feat = (const float*)d_in[i];
        else if (s == (long long)2 * E_)  idx  = (const int4*)d_in[i];
        else if (s == T_ * F_)            kern = (const float*)d_in[i];
        else if (s == F_)                 bias = (const float*)d_in[i];
    }
    if (!feat) feat = (const float*)d_in[0];
    if (!idx)  idx  = (const int4*)d_in[1];
    if (!kern) kern = (const float*)d_in[n_in >= 5 ? 3 : 2];
    if (!bias) bias = (const float*)d_in[n_in >= 5 ? 4 : 3];

    float* out = (float*)d_out;
    (void)out_size;

    scatter_kernel<<<(E_ / 2) / 256, 256>>>(feat, idx);
    gemm_kernel<<<N_ / 32, 256>>>(kern, bias, out);
}

// round 5
// speedup vs baseline: 1.0317x; 1.0317x over previous
#include <cuda_runtime.h>
#include <cstdint>

// Problem constants (fixed by the dataset)
#define T_ 8
#define E_ 8388608
#define N_ 262144
#define F_ 64

// 8 MB scratch for segment sums, layout agg[n][t] row-major (32B per node).
// Zero-initialized at module load; gemm_kernel re-zeros it after consuming,
// so every kernel_launch invocation (and every graph replay) sees zeros.
__device__ float g_agg[(size_t)N_ * T_];

// ---------------------------------------------------------------------------
// Scatter-add: 4 edges per thread.
// Per thread: 2x int4 index loads (4 int32 pairs), 8x float4 feature loads
// (coalesced 512B/warp per t), 8x red.global.add.v4.f32 into L2-resident agg.
// REDs are fire-and-forget; lo-half REDs can issue after the first 4 loads.
// ---------------------------------------------------------------------------
__global__ void scatter_kernel(const float* __restrict__ feat,
                               const int4* __restrict__ idx) {
    int i = blockIdx.x * blockDim.x + threadIdx.x;     // quad index, < E_/4
    size_t e = (size_t)i * 4;

    int4 p0 = __ldcs(&idx[2 * i]);       // edges e, e+1: (r0,c0,r1,c1)
    int4 p1 = __ldcs(&idx[2 * i + 1]);   // edges e+2, e+3
    int r0 = p0.x & (N_ - 1);
    int r1 = p0.z & (N_ - 1);
    int r2 = p1.x & (N_ - 1);
    int r3 = p1.z & (N_ - 1);

    float* d0 = g_agg + (size_t)r0 * T_;
    float* d1 = g_agg + (size_t)r1 * T_;
    float* d2 = g_agg + (size_t)r2 * T_;
    float* d3 = g_agg + (size_t)r3 * T_;

    float4 f[T_];
    #pragma unroll
    for (int t = 0; t < 4; ++t)
        f[t] = __ldcs(reinterpret_cast<const float4*>(feat + (size_t)t * E_ + e));

    // lo half (t=0..3) for each of the 4 edges
    asm volatile("red.global.add.v4.f32 [%0], {%1,%2,%3,%4};"
                 :: "l"(d0), "f"(f[0].x), "f"(f[1].x), "f"(f[2].x), "f"(f[3].x) : "memory");
    asm volatile("red.global.add.v4.f32 [%0], {%1,%2,%3,%4};"
                 :: "l"(d1), "f"(f[0].y), "f"(f[1].y), "f"(f[2].y), "f"(f[3].y) : "memory");
    asm volatile("red.global.add.v4.f32 [%0], {%1,%2,%3,%4};"
                 :: "l"(d2), "f"(f[0].z), "f"(f[1].z), "f"(f[2].z), "f"(f[3].z) : "memory");
    asm volatile("red.global.add.v4.f32 [%0], {%1,%2,%3,%4};"
                 :: "l"(d3), "f"(f[0].w), "f"(f[1].w), "f"(f[2].w), "f"(f[3].w) : "memory");

    #pragma unroll
    for (int t = 4; t < 8; ++t)
        f[t] = __ldcs(reinterpret_cast<const float4*>(feat + (size_t)t * E_ + e));

    // hi half (t=4..7)
    asm volatile("red.global.add.v4.f32 [%0], {%1,%2,%3,%4};"
                 :: "l"(d0 + 4), "f"(f[4].x), "f"(f[5].x), "f"(f[6].x), "f"(f[7].x) : "memory");
    asm volatile("red.global.add.v4.f32 [%0], {%1,%2,%3,%4};"
                 :: "l"(d1 + 4), "f"(f[4].y), "f"(f[5].y), "f"(f[6].y), "f"(f[7].y) : "memory");
    asm volatile("red.global.add.v4.f32 [%0], {%1,%2,%3,%4};"
                 :: "l"(d2 + 4), "f"(f[4].z), "f"(f[5].z), "f"(f[6].z), "f"(f[7].z) : "memory");
    asm volatile("red.global.add.v4.f32 [%0], {%1,%2,%3,%4};"
                 :: "l"(d3 + 4), "f"(f[4].w), "f"(f[5].w), "f"(f[6].w), "f"(f[7].w) : "memory");
}

// ---------------------------------------------------------------------------
// GEMM: out[n,f] = sum_t agg[n,t]*K[t,f] + bias[f].
// Each lane owns a fixed f-quad (q = lane&15) and holds K[0..7][4q..4q+3]
// in 32 registers. Warp = 2 nodes x 16 quads per iteration, grid-stride.
// Per node-quad: 2 broadcast LDG.128 (agg row), 32 FMA, 1 coalesced STG.128.
// Also re-zeros agg (consume-and-zero) so the next replay starts clean.
// ---------------------------------------------------------------------------
__global__ void gemm_kernel(const float* __restrict__ kern,
                            const float* __restrict__ bias,
                            float* __restrict__ out) {
    int lane = threadIdx.x & 31;
    int q    = lane & 15;     // f-quad 0..15
    int nsub = lane >> 4;     // 0..1

    float4 k4[T_];
    #pragma unroll
    for (int t = 0; t < T_; ++t)
        k4[t] = reinterpret_cast<const float4*>(kern)[t * 16 + q];
    float4 b4 = reinterpret_cast<const float4*>(bias)[q];

    int warp_global = (blockIdx.x * blockDim.x + threadIdx.x) >> 5;
    int nwarps = (gridDim.x * blockDim.x) >> 5;

    for (int base = warp_global * 2; base < N_; base += nwarps * 2) {
        int n = base + nsub;
        float4* arow = reinterpret_cast<float4*>(g_agg + (size_t)n * T_);
        float4 a0 = arow[0];      // uniform across the 16 lanes of this node
        float4 a1 = arow[1];

        float4 acc = b4;
        acc.x = fmaf(a0.x, k4[0].x, acc.x); acc.y = fmaf(a0.x, k4[0].y, acc.y);
        acc.z = fmaf(a0.x, k4[0].z, acc.z); acc.w = fmaf(a0.x, k4[0].w, acc.w);
        acc.x = fmaf(a0.y, k4[1].x, acc.x); acc.y = fmaf(a0.y, k4[1].y, acc.y);
        acc.z = fmaf(a0.y, k4[1].z, acc.z); acc.w = fmaf(a0.y, k4[1].w, acc.w);
        acc.x = fmaf(a0.z, k4[2].x, acc.x); acc.y = fmaf(a0.z, k4[2].y, acc.y);
        acc.z = fmaf(a0.z, k4[2].z, acc.z); acc.w = fmaf(a0.z, k4[2].w, acc.w);
        acc.x = fmaf(a0.w, k4[3].x, acc.x); acc.y = fmaf(a0.w, k4[3].y, acc.y);
        acc.z = fmaf(a0.w, k4[3].z, acc.z); acc.w = fmaf(a0.w, k4[3].w, acc.w);
        acc.x = fmaf(a1.x, k4[4].x, acc.x); acc.y = fmaf(a1.x, k4[4].y, acc.y);
        acc.z = fmaf(a1.x, k4[4].z, acc.z); acc.w = fmaf(a1.x, k4[4].w, acc.w);
        acc.x = fmaf(a1.y, k4[5].x, acc.x); acc.y = fmaf(a1.y, k4[5].y, acc.y);
        acc.z = fmaf(a1.y, k4[5].z, acc.z); acc.w = fmaf(a1.y, k4[5].w, acc.w);
        acc.x = fmaf(a1.z, k4[6].x, acc.x); acc.y = fmaf(a1.z, k4[6].y, acc.y);
        acc.z = fmaf(a1.z, k4[6].z, acc.z); acc.w = fmaf(a1.z, k4[6].w, acc.w);
        acc.x = fmaf(a1.w, k4[7].x, acc.x); acc.y = fmaf(a1.w, k4[7].y, acc.y);
        acc.z = fmaf(a1.w, k4[7].z, acc.z); acc.w = fmaf(a1.w, k4[7].w, acc.w);

        reinterpret_cast<float4*>(out)[(size_t)n * 16 + q] = acc;

        // consume-and-zero: lanes q==0/1 of each node rewrite the 32B row.
        __syncwarp();
        if (q < 2)
            arow[q] = make_float4(0.f, 0.f, 0.f, 0.f);
    }
}

// ---------------------------------------------------------------------------
// Launch contract — inputs resolved BY ELEMENT COUNT (robust to whether the
// scalar `out_size` occupies an input slot):
//   edge_features:  T*E = 67108864 f32
//   sparse_indices: E*2 = 16777216 i32
//   kernel:         T*F = 512 f32
//   bias:           F   = 64 f32
// Output: N*F f32.
// ---------------------------------------------------------------------------
extern "C" void kernel_launch(void* const* d_in, const int* in_sizes, int n_in,
                              void* d_out, int out_size) {
    const float* feat = nullptr;
    const int4*  idx  = nullptr;
    const float* kern = nullptr;
    const float* bias = nullptr;

    for (int i = 0; i < n_in; ++i) {
        long long s = in_sizes[i];
        if      (s == (long long)T_ * E_) feat = (const float*)d_in[i];
        else if (s == (long long)2 * E_)  idx  = (const int4*)d_in[i];
        else if (s == T_ * F_)            kern = (const float*)d_in[i];
        else if (s == F_)                 bias = (const float*)d_in[i];
    }
    if (!feat) feat = (const float*)d_in[0];
    if (!idx)  idx  = (const int4*)d_in[1];
    if (!kern) kern = (const float*)d_in[n_in >= 5 ? 3 : 2];
    if (!bias) bias = (const float*)d_in[n_in >= 5 ? 4 : 3];

    float* out = (float*)d_out;
    (void)out_size;

    scatter_kernel<<<(E_ / 4) / 256, 256>>>(feat, idx);
    gemm_kernel<<<2048, 256>>>(kern, bias, out);
}